// round 15
// baseline (speedup 1.0000x reference)
#include <cuda_runtime.h>
#include <cstddef>
#include <cstdint>

#define SEQ 4096
#define DIM 1024
#define NHEAD 16
#define HDIM 64

__device__ float g_qkv[(size_t)SEQ * 3 * DIM];   // [T, 3D]
__device__ float g_y[(size_t)SEQ * DIM];         // [T, D]

__device__ __forceinline__ unsigned f2tf(float f) {
    unsigned u;
    asm("cvt.rna.tf32.f32 %0, %1;" : "=r"(u) : "f"(f));
    return u;
}
__device__ __forceinline__ unsigned bits2tf(unsigned b) {
    return f2tf(__uint_as_float(b));
}

__device__ __forceinline__ void mma_tf32(float c[4], const unsigned a[4], const unsigned b[2]) {
    asm volatile(
        "mma.sync.aligned.m16n8k8.row.col.f32.tf32.tf32.f32 "
        "{%0,%1,%2,%3}, {%4,%5,%6,%7}, {%8,%9}, {%0,%1,%2,%3};"
        : "+f"(c[0]), "+f"(c[1]), "+f"(c[2]), "+f"(c[3])
        : "r"(a[0]), "r"(a[1]), "r"(a[2]), "r"(a[3]), "r"(b[0]), "r"(b[1]));
}

__device__ __forceinline__ uint32_t smem_u32(const void* p) {
    return (uint32_t)__cvta_generic_to_shared(p);
}

__device__ __forceinline__ void cp16(void* smem_dst, const void* gsrc) {
    unsigned d = (unsigned)__cvta_generic_to_shared(smem_dst);
    asm volatile("cp.async.cg.shared.global [%0], [%1], 16;" :: "r"(d), "l"(gsrc) : "memory");
}
#define CP_COMMIT() asm volatile("cp.async.commit_group;" ::: "memory")
#define CP_WAIT1()  asm volatile("cp.async.wait_group 1;" ::: "memory")

// ldmatrix.x4 of b16 8x8 tiles == four 8x4 tf32 tiles in mma frag layout.
#define LDSM4(r0, r1, r2, r3, addr)                                              \
    asm volatile("ldmatrix.sync.aligned.m8n8.x4.shared.b16 {%0,%1,%2,%3}, [%4];" \
                 : "=r"(r0), "=r"(r1), "=r"(r2), "=r"(r3) : "r"(addr))

// ===========================================================================
// TF32 GEMM "NT" (unchanged from R14): C[m][n] = sum_k A[m][k]*B[n][k]
// 128x128 tile, KT=32, 8 warps, cp.async double buffer, LDSM frags,
// cvt.rna after LDSM. launch_bounds(256,2).
// ===========================================================================
#define GST 36
#define GTILE (128 * GST)

__global__ __launch_bounds__(256, 2) void gemm_tf32_lm(const float* __restrict__ A,
                                                       const float* __restrict__ B,
                                                       float* __restrict__ C,
                                                       int M, int N, int K)
{
    extern __shared__ float sm[];

    const int tid  = threadIdx.x;
    const int lane = tid & 31;
    const int warp = tid >> 5;
    const int wm = warp & 1;
    const int wn = warp >> 1;
    const int bm = blockIdx.y * 128;
    const int bn = blockIdx.x * 128;
    const int g = lane >> 2;
    const int r = lane & 3;

    const int srow = tid >> 3;
    const int sc4  = tid & 7;

    auto stage = [&](int kt, int buf) {
        const float* Ap = A + (size_t)(bm + srow) * K + kt * 32 + sc4 * 4;
        const float* Bp = B + (size_t)(bn + srow) * K + kt * 32 + sc4 * 4;
        float* Ad = sm + buf * 2 * GTILE;
        float* Bd = Ad + GTILE;
#pragma unroll
        for (int t = 0; t < 4; ++t) {
            int row = srow + 32 * t;
            cp16(&Ad[row * GST + sc4 * 4], Ap + (size_t)(32 * t) * K);
            cp16(&Bd[row * GST + sc4 * 4], Bp + (size_t)(32 * t) * K);
        }
    };

    float acc[4][4][4];
#pragma unroll
    for (int mi = 0; mi < 4; ++mi)
#pragma unroll
        for (int nj = 0; nj < 4; ++nj)
#pragma unroll
            for (int e = 0; e < 4; ++e) acc[mi][nj][e] = 0.f;

    const uint32_t aoff =
        (uint32_t)(((wm * 64 + ((lane >> 3) & 1) * 8 + (lane & 7)) * GST + (lane >> 4) * 4) * 4);
    const uint32_t boff =
        (uint32_t)(((wn * 32 + (lane >> 4) * 8 + (lane & 7)) * GST + ((lane >> 3) & 1) * 4) * 4);

    const int nt = K / 32;
    stage(0, 0);
    CP_COMMIT();

    for (int kt = 0; kt < nt; ++kt) {
        const int buf = kt & 1;
        if (kt + 1 < nt) stage(kt + 1, buf ^ 1);
        CP_COMMIT();
        CP_WAIT1();
        __syncthreads();

        const uint32_t Abase = smem_u32(sm + buf * 2 * GTILE);
        const uint32_t Bbase = Abase + GTILE * 4;

#pragma unroll
        for (int kk = 0; kk < 4; ++kk) {
            const uint32_t ko = kk * 32;
            unsigned af[4][4];
#pragma unroll
            for (int mi = 0; mi < 4; ++mi)
                LDSM4(af[mi][0], af[mi][1], af[mi][2], af[mi][3],
                      Abase + aoff + mi * (16 * GST * 4) + ko);
            unsigned bf[4][2];
            LDSM4(bf[0][0], bf[0][1], bf[1][0], bf[1][1], Bbase + boff + ko);
            LDSM4(bf[2][0], bf[2][1], bf[3][0], bf[3][1],
                  Bbase + boff + 16 * GST * 4 + ko);
#pragma unroll
            for (int mi = 0; mi < 4; ++mi)
#pragma unroll
                for (int e = 0; e < 4; ++e) af[mi][e] = bits2tf(af[mi][e]);
#pragma unroll
            for (int nj = 0; nj < 4; ++nj) {
                bf[nj][0] = bits2tf(bf[nj][0]);
                bf[nj][1] = bits2tf(bf[nj][1]);
            }
#pragma unroll
            for (int mi = 0; mi < 4; ++mi)
#pragma unroll
                for (int nj = 0; nj < 4; ++nj)
                    mma_tf32(acc[mi][nj], af[mi], bf[nj]);
        }
        __syncthreads();
    }

#pragma unroll
    for (int mi = 0; mi < 4; ++mi) {
        int m = bm + wm * 64 + mi * 16 + g;
#pragma unroll
        for (int nj = 0; nj < 4; ++nj) {
            int n = bn + wn * 32 + nj * 8 + 2 * r;
            *(float2*)&C[(size_t)m * N + n]       = make_float2(acc[mi][nj][0], acc[mi][nj][1]);
            *(float2*)&C[(size_t)(m + 8) * N + n] = make_float2(acc[mi][nj][2], acc[mi][nj][3]);
        }
    }
}

// ===========================================================================
// TF32 flash attention, causal. 64-query tile, 4 warps, heavy blocks first.
// NEW: cp.async double-buffered RAW K/V tiles (dynamic smem); cvt.rna after
// LDSM (K) / at scalar LDS (V); softmax scale folded into Q staging (exact).
// Buffers: K[2][64][68], V[2][64][72] raw fp32 = 71680 B dynamic smem.
// ===========================================================================
#define AKST 68
#define AVST 72
#define AKBUF (64 * AKST)
#define AVBUF (64 * AVST)
#define ATTN_SMEM ((2 * AKBUF + 2 * AVBUF) * 4)

__global__ __launch_bounds__(128) void attn_tf32(const float* __restrict__ qkv,
                                                 float* __restrict__ y)
{
    extern __shared__ float asmem[];   // [K0][K1][V0][V1]
    float* Kb[2] = { asmem, asmem + AKBUF };
    float* Vb[2] = { asmem + 2 * AKBUF, asmem + 2 * AKBUF + AVBUF };

    const int tid  = threadIdx.x;
    const int lane = tid & 31;
    const int warp = tid >> 5;
    const int qb = gridDim.x - 1 - blockIdx.x;   // heavy blocks first
    const int h  = blockIdx.y;
    const int g = lane >> 2;
    const int r = lane & 3;
    const int row0 = warp * 16;

    // A-type lane offset (Q frags), B-type lane offset (K frags), stride 68
    const uint32_t qoff =
        (uint32_t)(((row0 + ((lane >> 3) & 1) * 8 + (lane & 7)) * AKST + (lane >> 4) * 4) * 4);
    const uint32_t koff =
        (uint32_t)((((lane >> 4) * 8 + (lane & 7)) * AKST + ((lane >> 3) & 1) * 4) * 4);

    // ---- Stage Q raw (pre-scaled by 1/8: exact power-of-two) into Kb[0] ----
    {
        int row = tid >> 4;
        int c4  = tid & 15;
#pragma unroll
        for (int t = 0; t < 8; ++t) {
            int rr = row + t * 8;
            float4 v = *(const float4*)&qkv[(size_t)(qb * 64 + rr) * (3 * DIM) + h * HDIM + c4 * 4];
            float* d = &Kb[0][rr * AKST + c4 * 4];
            d[0] = v.x * 0.125f;
            d[1] = v.y * 0.125f;
            d[2] = v.z * 0.125f;
            d[3] = v.w * 0.125f;
        }
    }
    __syncthreads();

    unsigned qf[8][4];
    {
        const uint32_t K0b = smem_u32(Kb[0]);
#pragma unroll
        for (int kk = 0; kk < 8; ++kk) {
            LDSM4(qf[kk][0], qf[kk][1], qf[kk][2], qf[kk][3], K0b + qoff + kk * 32);
#pragma unroll
            for (int e = 0; e < 4; ++e) qf[kk][e] = bits2tf(qf[kk][e]);
        }
    }
    __syncthreads();   // done reading Kb[0] before prefetch overwrites it

    // ---- K/V staging via cp.async (raw fp32) ----
    auto stage = [&](int kt, int buf) {
        int row = tid >> 4;
        int c4  = tid & 15;
        float* Kd = Kb[buf];
        float* Vd = Vb[buf];
#pragma unroll
        for (int t = 0; t < 8; ++t) {
            int rr = row + t * 8;
            const float* base = &qkv[(size_t)(kt * 64 + rr) * (3 * DIM) + h * HDIM + c4 * 4];
            cp16(&Kd[rr * AKST + c4 * 4], base + DIM);
            cp16(&Vd[rr * AVST + c4 * 4], base + 2 * DIM);
        }
    };

    float oacc[8][4];
#pragma unroll
    for (int j = 0; j < 8; ++j)
#pragma unroll
        for (int e = 0; e < 4; ++e) oacc[j][e] = 0.f;

    float m_lo = -1e30f, m_hi = -1e30f, l_lo = 0.f, l_hi = 0.f;

    stage(0, 0);
    CP_COMMIT();

    for (int kt = 0; kt <= qb; ++kt) {
        const int buf = kt & 1;
        if (kt + 1 <= qb) stage(kt + 1, buf ^ 1);
        CP_COMMIT();
        CP_WAIT1();
        __syncthreads();

        const uint32_t Kbase = smem_u32(Kb[buf]);
        const float* Vp = Vb[buf];

        // ---- S = Q K^T : K frags via LDSM + cvt ----
        float s[8][4];
#pragma unroll
        for (int j = 0; j < 8; ++j)
#pragma unroll
            for (int e = 0; e < 4; ++e) s[j][e] = 0.f;

#pragma unroll
        for (int kk = 0; kk < 8; ++kk) {
            unsigned bK[8][2];
#pragma unroll
            for (int p = 0; p < 4; ++p)
                LDSM4(bK[2 * p][0], bK[2 * p][1], bK[2 * p + 1][0], bK[2 * p + 1][1],
                      Kbase + koff + p * (16 * AKST * 4) + kk * 32);
#pragma unroll
            for (int j = 0; j < 8; ++j) {
                bK[j][0] = bits2tf(bK[j][0]);
                bK[j][1] = bits2tf(bK[j][1]);
            }
#pragma unroll
            for (int j = 0; j < 8; ++j) mma_tf32(s[j], qf[kk], bK[j]);
        }

        // ---- mask + online softmax (scale already folded into Q) ----
        const bool diag = (kt == qb);
        float mx_lo = -1e30f, mx_hi = -1e30f;
#pragma unroll
        for (int j = 0; j < 8; ++j) {
#pragma unroll
            for (int e = 0; e < 2; ++e) {
                int col = j * 8 + 2 * r + e;
                float plo = s[j][e];
                float phi = s[j][2 + e];
                if (diag && col > row0 + g) plo = -1e30f;
                if (diag && col > row0 + 8 + g) phi = -1e30f;
                s[j][e] = plo;
                s[j][2 + e] = phi;
                mx_lo = fmaxf(mx_lo, plo);
                mx_hi = fmaxf(mx_hi, phi);
            }
        }
#pragma unroll
        for (int off = 1; off <= 2; off <<= 1) {
            mx_lo = fmaxf(mx_lo, __shfl_xor_sync(0xffffffffu, mx_lo, off));
            mx_hi = fmaxf(mx_hi, __shfl_xor_sync(0xffffffffu, mx_hi, off));
        }
        float mn_lo = fmaxf(m_lo, mx_lo);
        float mn_hi = fmaxf(m_hi, mx_hi);
        float sum_lo = 0.f, sum_hi = 0.f;
#pragma unroll
        for (int j = 0; j < 8; ++j) {
#pragma unroll
            for (int e = 0; e < 2; ++e) {
                s[j][e]     = __expf(s[j][e] - mn_lo);
                s[j][2 + e] = __expf(s[j][2 + e] - mn_hi);
                sum_lo += s[j][e];
                sum_hi += s[j][2 + e];
            }
        }
#pragma unroll
        for (int off = 1; off <= 2; off <<= 1) {
            sum_lo += __shfl_xor_sync(0xffffffffu, sum_lo, off);
            sum_hi += __shfl_xor_sync(0xffffffffu, sum_hi, off);
        }
        float al_lo = __expf(m_lo - mn_lo);
        float al_hi = __expf(m_hi - mn_hi);
        l_lo = l_lo * al_lo + sum_lo;
        l_hi = l_hi * al_hi + sum_hi;
        m_lo = mn_lo;
        m_hi = mn_hi;
#pragma unroll
        for (int j = 0; j < 8; ++j) {
            oacc[j][0] *= al_lo; oacc[j][1] *= al_lo;
            oacc[j][2] *= al_hi; oacc[j][3] *= al_hi;
        }

        // ---- P to tf32 ----
        unsigned pt[8][4];
#pragma unroll
        for (int j = 0; j < 8; ++j)
#pragma unroll
            for (int e = 0; e < 4; ++e) pt[j][e] = f2tf(s[j][e]);

        // ---- O += P V : A-frags via shuffles, V scalar LDS + cvt ----
        const int srcA = (lane & ~3) | (r >> 1);
        const int srcB = (lane & ~3) | (((r + 4) >> 1));
        const bool odd = (r & 1);
#pragma unroll
        for (int kk = 0; kk < 8; ++kk) {
            unsigned a[4];
            {
                unsigned t0 = __shfl_sync(0xffffffffu, pt[kk][0], srcA);
                unsigned t1 = __shfl_sync(0xffffffffu, pt[kk][1], srcA);
                unsigned t2 = __shfl_sync(0xffffffffu, pt[kk][0], srcB);
                unsigned t3 = __shfl_sync(0xffffffffu, pt[kk][1], srcB);
                a[0] = odd ? t1 : t0;
                a[2] = odd ? t3 : t2;
                t0 = __shfl_sync(0xffffffffu, pt[kk][2], srcA);
                t1 = __shfl_sync(0xffffffffu, pt[kk][3], srcA);
                t2 = __shfl_sync(0xffffffffu, pt[kk][2], srcB);
                t3 = __shfl_sync(0xffffffffu, pt[kk][3], srcB);
                a[1] = odd ? t1 : t0;
                a[3] = odd ? t3 : t2;
            }
#pragma unroll
            for (int j = 0; j < 8; ++j) {
                unsigned bV[2];
                bV[0] = f2tf(Vp[(kk * 8 + r) * AVST + j * 8 + g]);
                bV[1] = f2tf(Vp[(kk * 8 + r + 4) * AVST + j * 8 + g]);
                mma_tf32(oacc[j], a, bV);
            }
        }
        __syncthreads();
    }

    // ---- normalize + write ----
    float inv_lo = 1.f / l_lo;
    float inv_hi = 1.f / l_hi;
    int row_lo = qb * 64 + row0 + g;
#pragma unroll
    for (int j = 0; j < 8; ++j) {
        int n = h * HDIM + j * 8 + 2 * r;
        *(float2*)&y[(size_t)row_lo * DIM + n] =
            make_float2(oacc[j][0] * inv_lo, oacc[j][1] * inv_lo);
        *(float2*)&y[(size_t)(row_lo + 8) * DIM + n] =
            make_float2(oacc[j][2] * inv_hi, oacc[j][3] * inv_hi);
    }
}

// ---------------------------------------------------------------------------
extern "C" void kernel_launch(void* const* d_in, const int* in_sizes, int n_in,
                              void* d_out, int out_size)
{
    (void)in_sizes; (void)n_in; (void)out_size;
    const float* x      = (const float*)d_in[0];
    const float* w_attn = (const float*)d_in[1];
    const float* w_proj = (const float*)d_in[2];
    float* out = (float*)d_out;

    float* qkv_p = nullptr;
    float* y_p   = nullptr;
    cudaGetSymbolAddress((void**)&qkv_p, g_qkv);
    cudaGetSymbolAddress((void**)&y_p, g_y);

    const int gemm_smem = 4 * GTILE * (int)sizeof(float);   // 73728
    cudaFuncSetAttribute(gemm_tf32_lm, cudaFuncAttributeMaxDynamicSharedMemorySize, gemm_smem);
    cudaFuncSetAttribute(attn_tf32, cudaFuncAttributeMaxDynamicSharedMemorySize, ATTN_SMEM);

    {   // QKV: [4096,1024] x [3072,1024]^T -> [4096,3072]
        dim3 grid(3 * DIM / 128, SEQ / 128);
        gemm_tf32_lm<<<grid, 256, gemm_smem>>>(x, w_attn, qkv_p, SEQ, 3 * DIM, DIM);
    }
    {   // causal flash attention (64-query tiles), pipelined K/V
        dim3 grid(SEQ / 64, NHEAD);
        attn_tf32<<<grid, 128, ATTN_SMEM>>>(qkv_p, y_p);
    }
    {   // proj: [4096,1024] x [1024,1024]^T -> out
        dim3 grid(DIM / 128, SEQ / 128);
        gemm_tf32_lm<<<grid, 256, gemm_smem>>>(y_p, w_proj, out, SEQ, DIM, DIM);
    }
}

// round 16
// speedup vs baseline: 1.1562x; 1.1562x over previous
#include <cuda_runtime.h>
#include <cstddef>
#include <cstdint>

#define SEQ 4096
#define DIM 1024
#define NHEAD 16
#define HDIM 64

// Scratch (pre-rounded tf32 values stored as fp32 bit patterns)
__device__ float g_xtf[(size_t)SEQ * DIM];
__device__ float g_wattntf[(size_t)3 * DIM * DIM];
__device__ float g_wprojtf[(size_t)DIM * DIM];
__device__ float g_qkv[(size_t)SEQ * 3 * DIM];   // rounded QKV
__device__ float g_y[(size_t)SEQ * DIM];         // rounded attention out

__device__ __forceinline__ unsigned f2tf(float f) {
    unsigned u;
    asm("cvt.rna.tf32.f32 %0, %1;" : "=r"(u) : "f"(f));
    return u;
}

__device__ __forceinline__ void mma_tf32(float c[4], const unsigned a[4], const unsigned b[2]) {
    asm volatile(
        "mma.sync.aligned.m16n8k8.row.col.f32.tf32.tf32.f32 "
        "{%0,%1,%2,%3}, {%4,%5,%6,%7}, {%8,%9}, {%0,%1,%2,%3};"
        : "+f"(c[0]), "+f"(c[1]), "+f"(c[2]), "+f"(c[3])
        : "r"(a[0]), "r"(a[1]), "r"(a[2]), "r"(a[3]), "r"(b[0]), "r"(b[1]));
}

__device__ __forceinline__ uint32_t smem_u32(const void* p) {
    return (uint32_t)__cvta_generic_to_shared(p);
}

__device__ __forceinline__ void cp16(void* smem_dst, const void* gsrc) {
    unsigned d = (unsigned)__cvta_generic_to_shared(smem_dst);
    asm volatile("cp.async.cg.shared.global [%0], [%1], 16;" :: "r"(d), "l"(gsrc) : "memory");
}
#define CP_COMMIT() asm volatile("cp.async.commit_group;" ::: "memory")
#define CP_WAIT1()  asm volatile("cp.async.wait_group 1;" ::: "memory")

#define LDSM4(r0, r1, r2, r3, addr)                                              \
    asm volatile("ldmatrix.sync.aligned.m8n8.x4.shared.b16 {%0,%1,%2,%3}, [%4];" \
                 : "=r"(r0), "=r"(r1), "=r"(r2), "=r"(r3) : "r"(addr))

// ===========================================================================
// Pre-round an array to tf32 (rna), stored as fp32 bits. n % 4 == 0.
// ===========================================================================
__global__ __launch_bounds__(256) void cvt_tf32(const float* __restrict__ in,
                                                float* __restrict__ out, int n4)
{
    int i = blockIdx.x * 256 + threadIdx.x;
    if (i < n4) {
        float4 v = ((const float4*)in)[i];
        uint4 u = make_uint4(f2tf(v.x), f2tf(v.y), f2tf(v.z), f2tf(v.w));
        ((uint4*)out)[i] = u;
    }
}

// ===========================================================================
// TF32 GEMM "NT": C[m][n] = sum_k A[m][k]*B[n][k]
// Inputs PRE-ROUNDED to tf32: mainloop = 6 LDSM + 16 mma per kk, zero cvt.
// 128x128 tile, KT=32, 8 warps, cp.async double buffer. launch_bounds(256,2).
// round_out: epilogue stores rna(acc) (for qkv) or raw acc (final output).
// ===========================================================================
#define GST 36
#define GTILE (128 * GST)

__global__ __launch_bounds__(256, 2) void gemm_tf32_lm(const float* __restrict__ A,
                                                       const float* __restrict__ B,
                                                       float* __restrict__ C,
                                                       int M, int N, int K,
                                                       int round_out)
{
    extern __shared__ float sm[];

    const int tid  = threadIdx.x;
    const int lane = tid & 31;
    const int warp = tid >> 5;
    const int wm = warp & 1;
    const int wn = warp >> 1;
    const int bm = blockIdx.y * 128;
    const int bn = blockIdx.x * 128;
    const int g = lane >> 2;
    const int r = lane & 3;

    const int srow = tid >> 3;
    const int sc4  = tid & 7;

    auto stage = [&](int kt, int buf) {
        const float* Ap = A + (size_t)(bm + srow) * K + kt * 32 + sc4 * 4;
        const float* Bp = B + (size_t)(bn + srow) * K + kt * 32 + sc4 * 4;
        float* Ad = sm + buf * 2 * GTILE;
        float* Bd = Ad + GTILE;
#pragma unroll
        for (int t = 0; t < 4; ++t) {
            int row = srow + 32 * t;
            cp16(&Ad[row * GST + sc4 * 4], Ap + (size_t)(32 * t) * K);
            cp16(&Bd[row * GST + sc4 * 4], Bp + (size_t)(32 * t) * K);
        }
    };

    float acc[4][4][4];
#pragma unroll
    for (int mi = 0; mi < 4; ++mi)
#pragma unroll
        for (int nj = 0; nj < 4; ++nj)
#pragma unroll
            for (int e = 0; e < 4; ++e) acc[mi][nj][e] = 0.f;

    const uint32_t aoff =
        (uint32_t)(((wm * 64 + ((lane >> 3) & 1) * 8 + (lane & 7)) * GST + (lane >> 4) * 4) * 4);
    const uint32_t boff =
        (uint32_t)(((wn * 32 + (lane >> 4) * 8 + (lane & 7)) * GST + ((lane >> 3) & 1) * 4) * 4);

    const int nt = K / 32;
    stage(0, 0);
    CP_COMMIT();

    for (int kt = 0; kt < nt; ++kt) {
        const int buf = kt & 1;
        if (kt + 1 < nt) stage(kt + 1, buf ^ 1);
        CP_COMMIT();
        CP_WAIT1();
        __syncthreads();

        const uint32_t Abase = smem_u32(sm + buf * 2 * GTILE);
        const uint32_t Bbase = Abase + GTILE * 4;

#pragma unroll
        for (int kk = 0; kk < 4; ++kk) {
            const uint32_t ko = kk * 32;
            unsigned af[4][4];
#pragma unroll
            for (int mi = 0; mi < 4; ++mi)
                LDSM4(af[mi][0], af[mi][1], af[mi][2], af[mi][3],
                      Abase + aoff + mi * (16 * GST * 4) + ko);
            unsigned bf[4][2];
            LDSM4(bf[0][0], bf[0][1], bf[1][0], bf[1][1], Bbase + boff + ko);
            LDSM4(bf[2][0], bf[2][1], bf[3][0], bf[3][1],
                  Bbase + boff + 16 * GST * 4 + ko);
#pragma unroll
            for (int mi = 0; mi < 4; ++mi)
#pragma unroll
                for (int nj = 0; nj < 4; ++nj)
                    mma_tf32(acc[mi][nj], af[mi], bf[nj]);
        }
        __syncthreads();
    }

    // Epilogue (optionally tf32-round the output for downstream consumers)
#pragma unroll
    for (int mi = 0; mi < 4; ++mi) {
        int m = bm + wm * 64 + mi * 16 + g;
#pragma unroll
        for (int nj = 0; nj < 4; ++nj) {
            int n = bn + wn * 32 + nj * 8 + 2 * r;
            if (round_out) {
                *(float2*)&C[(size_t)m * N + n] =
                    make_float2(__uint_as_float(f2tf(acc[mi][nj][0])),
                                __uint_as_float(f2tf(acc[mi][nj][1])));
                *(float2*)&C[(size_t)(m + 8) * N + n] =
                    make_float2(__uint_as_float(f2tf(acc[mi][nj][2])),
                                __uint_as_float(f2tf(acc[mi][nj][3])));
            } else {
                *(float2*)&C[(size_t)m * N + n]       = make_float2(acc[mi][nj][0], acc[mi][nj][1]);
                *(float2*)&C[(size_t)(m + 8) * N + n] = make_float2(acc[mi][nj][2], acc[mi][nj][3]);
            }
        }
    }
}

// ===========================================================================
// TF32 flash attention, causal (R14 structure: 64-query tile, 4 warps,
// static smem, heavy blocks first). qkv is PRE-ROUNDED: staging is pure
// copies, zero cvt in staging / S / PV. Only P needs f2tf.
// Epilogue stores rna(o/l) so proj loads raw.
// ===========================================================================
__global__ __launch_bounds__(128) void attn_tf32(const float* __restrict__ qkv,
                                                 float* __restrict__ y)
{
    __shared__ float Ks[64][68];
    __shared__ float Vs[64][72];

    const int tid  = threadIdx.x;
    const int lane = tid & 31;
    const int warp = tid >> 5;
    const int qb = gridDim.x - 1 - blockIdx.x;   // heavy blocks first
    const int h  = blockIdx.y;
    const int g = lane >> 2;
    const int r = lane & 3;
    const int row0 = warp * 16;

    const uint32_t Ksb = smem_u32(&Ks[0][0]);
    const uint32_t qoff =
        (uint32_t)(((row0 + ((lane >> 3) & 1) * 8 + (lane & 7)) * 68 + (lane >> 4) * 4) * 4);
    const uint32_t koff =
        (uint32_t)((((lane >> 4) * 8 + (lane & 7)) * 68 + ((lane >> 3) & 1) * 4) * 4);

    // ---- Stage Q (pre-rounded) scaled by 1/8 (exact exponent shift) ----
#pragma unroll
    for (int t = 0; t < 8; ++t) {
        int idx = tid + t * 128;
        int row = idx >> 4;
        int c4  = idx & 15;
        float4 v = *(const float4*)&qkv[(size_t)(qb * 64 + row) * (3 * DIM) + h * HDIM + c4 * 4];
        float* d = &Ks[row][c4 * 4];
        d[0] = v.x * 0.125f;
        d[1] = v.y * 0.125f;
        d[2] = v.z * 0.125f;
        d[3] = v.w * 0.125f;
    }
    __syncthreads();

    unsigned qf[8][4];
#pragma unroll
    for (int kk = 0; kk < 8; ++kk)
        LDSM4(qf[kk][0], qf[kk][1], qf[kk][2], qf[kk][3], Ksb + qoff + kk * 32);
    __syncthreads();

    float oacc[8][4];
#pragma unroll
    for (int j = 0; j < 8; ++j)
#pragma unroll
        for (int e = 0; e < 4; ++e) oacc[j][e] = 0.f;

    float m_lo = -1e30f, m_hi = -1e30f, l_lo = 0.f, l_hi = 0.f;

    for (int kt = 0; kt <= qb; ++kt) {
        // ---- Stage K/V: pure uint4 copies (data already tf32-rounded) ----
#pragma unroll
        for (int t = 0; t < 8; ++t) {
            int idx = tid + t * 128;
            int row = idx >> 4;
            int c4  = idx & 15;
            size_t base = (size_t)(kt * 64 + row) * (3 * DIM) + h * HDIM + c4 * 4;
            *(uint4*)&Ks[row][c4 * 4] = *(const uint4*)&qkv[base + DIM];
            *(uint4*)&Vs[row][c4 * 4] = *(const uint4*)&qkv[base + 2 * DIM];
        }
        __syncthreads();

        // ---- S = Q K^T : K frags via LDSM, no cvt ----
        float s[8][4];
#pragma unroll
        for (int j = 0; j < 8; ++j)
#pragma unroll
            for (int e = 0; e < 4; ++e) s[j][e] = 0.f;

#pragma unroll
        for (int kk = 0; kk < 8; ++kk) {
            unsigned bK[8][2];
#pragma unroll
            for (int p = 0; p < 4; ++p)
                LDSM4(bK[2 * p][0], bK[2 * p][1], bK[2 * p + 1][0], bK[2 * p + 1][1],
                      Ksb + koff + p * (16 * 68 * 4) + kk * 32);
#pragma unroll
            for (int j = 0; j < 8; ++j) mma_tf32(s[j], qf[kk], bK[j]);
        }

        // ---- mask + online softmax (scale folded into Q) ----
        const bool diag = (kt == qb);
        float mx_lo = -1e30f, mx_hi = -1e30f;
#pragma unroll
        for (int j = 0; j < 8; ++j) {
#pragma unroll
            for (int e = 0; e < 2; ++e) {
                int col = j * 8 + 2 * r + e;
                float plo = s[j][e];
                float phi = s[j][2 + e];
                if (diag && col > row0 + g) plo = -1e30f;
                if (diag && col > row0 + 8 + g) phi = -1e30f;
                s[j][e] = plo;
                s[j][2 + e] = phi;
                mx_lo = fmaxf(mx_lo, plo);
                mx_hi = fmaxf(mx_hi, phi);
            }
        }
#pragma unroll
        for (int off = 1; off <= 2; off <<= 1) {
            mx_lo = fmaxf(mx_lo, __shfl_xor_sync(0xffffffffu, mx_lo, off));
            mx_hi = fmaxf(mx_hi, __shfl_xor_sync(0xffffffffu, mx_hi, off));
        }
        float mn_lo = fmaxf(m_lo, mx_lo);
        float mn_hi = fmaxf(m_hi, mx_hi);
        float sum_lo = 0.f, sum_hi = 0.f;
#pragma unroll
        for (int j = 0; j < 8; ++j) {
#pragma unroll
            for (int e = 0; e < 2; ++e) {
                s[j][e]     = __expf(s[j][e] - mn_lo);
                s[j][2 + e] = __expf(s[j][2 + e] - mn_hi);
                sum_lo += s[j][e];
                sum_hi += s[j][2 + e];
            }
        }
#pragma unroll
        for (int off = 1; off <= 2; off <<= 1) {
            sum_lo += __shfl_xor_sync(0xffffffffu, sum_lo, off);
            sum_hi += __shfl_xor_sync(0xffffffffu, sum_hi, off);
        }
        float al_lo = __expf(m_lo - mn_lo);
        float al_hi = __expf(m_hi - mn_hi);
        l_lo = l_lo * al_lo + sum_lo;
        l_hi = l_hi * al_hi + sum_hi;
        m_lo = mn_lo;
        m_hi = mn_hi;
#pragma unroll
        for (int j = 0; j < 8; ++j) {
            oacc[j][0] *= al_lo; oacc[j][1] *= al_lo;
            oacc[j][2] *= al_hi; oacc[j][3] *= al_hi;
        }

        // ---- P to tf32 (the one remaining cvt) ----
        unsigned pt[8][4];
#pragma unroll
        for (int j = 0; j < 8; ++j)
#pragma unroll
            for (int e = 0; e < 4; ++e) pt[j][e] = f2tf(s[j][e]);

        // ---- O += P V : A-frags via shuffles, V scalar loads (no cvt) ----
        const int srcA = (lane & ~3) | (r >> 1);
        const int srcB = (lane & ~3) | (((r + 4) >> 1));
        const bool odd = (r & 1);
#pragma unroll
        for (int kk = 0; kk < 8; ++kk) {
            unsigned a[4];
            {
                unsigned t0 = __shfl_sync(0xffffffffu, pt[kk][0], srcA);
                unsigned t1 = __shfl_sync(0xffffffffu, pt[kk][1], srcA);
                unsigned t2 = __shfl_sync(0xffffffffu, pt[kk][0], srcB);
                unsigned t3 = __shfl_sync(0xffffffffu, pt[kk][1], srcB);
                a[0] = odd ? t1 : t0;
                a[2] = odd ? t3 : t2;
                t0 = __shfl_sync(0xffffffffu, pt[kk][2], srcA);
                t1 = __shfl_sync(0xffffffffu, pt[kk][3], srcA);
                t2 = __shfl_sync(0xffffffffu, pt[kk][2], srcB);
                t3 = __shfl_sync(0xffffffffu, pt[kk][3], srcB);
                a[1] = odd ? t1 : t0;
                a[3] = odd ? t3 : t2;
            }
#pragma unroll
            for (int j = 0; j < 8; ++j) {
                unsigned bV[2];
                bV[0] = __float_as_uint(Vs[kk * 8 + r][j * 8 + g]);
                bV[1] = __float_as_uint(Vs[kk * 8 + r + 4][j * 8 + g]);
                mma_tf32(oacc[j], a, bV);
            }
        }
        __syncthreads();
    }

    // ---- normalize + write, pre-rounded for the proj GEMM ----
    float inv_lo = 1.f / l_lo;
    float inv_hi = 1.f / l_hi;
    int row_lo = qb * 64 + row0 + g;
#pragma unroll
    for (int j = 0; j < 8; ++j) {
        int n = h * HDIM + j * 8 + 2 * r;
        *(float2*)&y[(size_t)row_lo * DIM + n] =
            make_float2(__uint_as_float(f2tf(oacc[j][0] * inv_lo)),
                        __uint_as_float(f2tf(oacc[j][1] * inv_lo)));
        *(float2*)&y[(size_t)(row_lo + 8) * DIM + n] =
            make_float2(__uint_as_float(f2tf(oacc[j][2] * inv_hi)),
                        __uint_as_float(f2tf(oacc[j][3] * inv_hi)));
    }
}

// ---------------------------------------------------------------------------
extern "C" void kernel_launch(void* const* d_in, const int* in_sizes, int n_in,
                              void* d_out, int out_size)
{
    (void)in_sizes; (void)n_in; (void)out_size;
    const float* x      = (const float*)d_in[0];
    const float* w_attn = (const float*)d_in[1];
    const float* w_proj = (const float*)d_in[2];
    float* out = (float*)d_out;

    float *xtf_p, *wattn_p, *wproj_p, *qkv_p, *y_p;
    cudaGetSymbolAddress((void**)&xtf_p, g_xtf);
    cudaGetSymbolAddress((void**)&wattn_p, g_wattntf);
    cudaGetSymbolAddress((void**)&wproj_p, g_wprojtf);
    cudaGetSymbolAddress((void**)&qkv_p, g_qkv);
    cudaGetSymbolAddress((void**)&y_p, g_y);

    const int gemm_smem = 4 * GTILE * (int)sizeof(float);   // 73728
    cudaFuncSetAttribute(gemm_tf32_lm, cudaFuncAttributeMaxDynamicSharedMemorySize, gemm_smem);

    // 0) Pre-round inputs to tf32
    {
        int n4x = SEQ * DIM / 4;
        cvt_tf32<<<(n4x + 255) / 256, 256>>>(x, xtf_p, n4x);
        int n4a = 3 * DIM * DIM / 4;
        cvt_tf32<<<(n4a + 255) / 256, 256>>>(w_attn, wattn_p, n4a);
        int n4p = DIM * DIM / 4;
        cvt_tf32<<<(n4p + 255) / 256, 256>>>(w_proj, wproj_p, n4p);
    }
    {   // 1) QKV: [4096,1024] x [3072,1024]^T -> rounded qkv
        dim3 grid(3 * DIM / 128, SEQ / 128);
        gemm_tf32_lm<<<grid, 256, gemm_smem>>>(xtf_p, wattn_p, qkv_p, SEQ, 3 * DIM, DIM, 1);
    }
    {   // 2) causal flash attention -> rounded y
        dim3 grid(SEQ / 64, NHEAD);
        attn_tf32<<<grid, 128>>>(qkv_p, y_p);
    }
    {   // 3) proj: [4096,1024] x [1024,1024]^T -> out (raw fp32)
        dim3 grid(DIM / 128, SEQ / 128);
        gemm_tf32_lm<<<grid, 256, gemm_smem>>>(y_p, wproj_p, out, SEQ, DIM, DIM, 0);
    }
}